// round 6
// baseline (speedup 1.0000x reference)
#include <cuda_runtime.h>
#include <cstdint>
#include <math.h>

#define D 128
#define NU_MAX 100000
#define NI_MAX 50000
#define KC 64

// ---------------- scratch (device globals; no allocation allowed) ----------------
__device__ float4 g_agg_user4[(size_t)NU_MAX * D / 4];  // Σ norm_i2u * feat_item[src] per user
__device__ float4 g_agg_item4[(size_t)NI_MAX * D / 4];  // Σ norm_u2i * feat_user[src] per item
__device__ float  g_deg_user[NU_MAX];
__device__ float  g_deg_item[NI_MAX];

// ---------------- zero the scratch ----------------
__global__ void zero_all_kernel() {
    size_t i = (size_t)blockIdx.x * blockDim.x + threadIdx.x;
    size_t stride = (size_t)gridDim.x * blockDim.x;
    const float4 z = make_float4(0.f, 0.f, 0.f, 0.f);
    const size_t nu4 = (size_t)NU_MAX * D / 4;
    const size_t ni4 = (size_t)NI_MAX * D / 4;
    for (size_t j = i; j < nu4; j += stride) g_agg_user4[j] = z;
    for (size_t j = i; j < ni4; j += stride) g_agg_item4[j] = z;
    for (size_t j = i; j < NU_MAX; j += stride) g_deg_user[j] = 0.f;
    for (size_t j = i; j < NI_MAX; j += stride) g_deg_item[j] = 0.f;
}

// ---------------- per-edge scatter: agg[dst] += norm * feat_src[src] ----------------
// One warp per edge: lane l owns floats [4l, 4l+4). red.global.add.v4.f32 keeps the
// atomic instruction count at 1 per lane per edge (16B each).
template <int TO_ITEM>
__global__ void scatter_kernel(const float* __restrict__ feat_src,
                               const int* __restrict__ src,
                               const int* __restrict__ dst,
                               const float* __restrict__ norm,
                               int E) {
    int warp = (blockIdx.x * blockDim.x + threadIdx.x) >> 5;
    int lane = threadIdx.x & 31;
    if (warp >= E) return;
    int s = __ldg(src + warp);
    int d = __ldg(dst + warp);
    float w = __ldg(norm + warp);
    float4 f = __ldg(((const float4*)(feat_src + (size_t)s * D)) + lane);
    float* agg = TO_ITEM ? (float*)g_agg_item4 : (float*)g_agg_user4;
    float* deg = TO_ITEM ? g_deg_item : g_deg_user;
    float* addr = agg + (size_t)d * D + lane * 4;
    asm volatile("red.global.add.v4.f32 [%0], {%1, %2, %3, %4};"
                 :: "l"(addr), "f"(w * f.x), "f"(w * f.y), "f"(w * f.z), "f"(w * f.w)
                 : "memory");
    if (lane == 0) atomicAdd(deg + d, w);
}

// ---------------- fused dual-GEMM + bias + LeakyReLU + row L2-normalize ----------------
// Block: 128 rows x 128 cols output.  h = A@W1 + B@W2 + (1+deg)*b1 + deg*b2
// where A = feat+agg, B = feat*agg (staged transposed in smem for vectorized k-major reads).
// W1/W2 streamed in KC=64 k-chunks (L2-hot). 256 threads, 8x8 register tile each.
// Full 128-col row is inside the block -> row norm reduced with shfl_xor over the
// 16 lanes sharing a row group, epilogue fully in registers.
template <int IS_USER>
__global__ __launch_bounds__(256, 1)
void gemm_finish_kernel(const float* __restrict__ feat,
                        const float* __restrict__ W1,
                        const float* __restrict__ b1,
                        const float* __restrict__ W2,
                        const float* __restrict__ b2,
                        float* __restrict__ out,
                        int Nrows) {
    extern __shared__ float smem[];
    float* At  = smem;              // [128][128]  A transposed: At[k][r]
    float* Bt  = At + 128 * 128;    // [128][128]
    float* W1c = Bt + 128 * 128;    // [KC][128]
    float* W2c = W1c + KC * 128;    // [KC][128]

    const float* agg = IS_USER ? (const float*)g_agg_user4 : (const float*)g_agg_item4;
    const float* deg = IS_USER ? g_deg_user : g_deg_item;

    const int row0 = blockIdx.x * 128;
    const int tid = threadIdx.x;

    // ---- stage A/B (transposed) ----
    {
        int r = tid >> 1;
        int half = tid & 1;
        int grow = row0 + r;
        bool valid = grow < Nrows;
        const float4* fp = (const float4*)(feat + (size_t)grow * D) + half * 16;
        const float4* ap = (const float4*)(agg + (size_t)grow * D) + half * 16;
        #pragma unroll
        for (int j = 0; j < 16; ++j) {
            float4 f = valid ? __ldg(fp + j) : make_float4(0.f, 0.f, 0.f, 0.f);
            float4 a = valid ? __ldg(ap + j) : make_float4(0.f, 0.f, 0.f, 0.f);
            int k = half * 64 + j * 4;
            At[(k + 0) * 128 + r] = f.x + a.x;  Bt[(k + 0) * 128 + r] = f.x * a.x;
            At[(k + 1) * 128 + r] = f.y + a.y;  Bt[(k + 1) * 128 + r] = f.y * a.y;
            At[(k + 2) * 128 + r] = f.z + a.z;  Bt[(k + 2) * 128 + r] = f.z * a.z;
            At[(k + 3) * 128 + r] = f.w + a.w;  Bt[(k + 3) * 128 + r] = f.w * a.w;
        }
    }

    const int cg = tid & 15;        // column group  -> cols [cg*8, cg*8+8)
    const int rg = tid >> 4;        // row group     -> rows [rg*8, rg*8+8)
    const int c0 = cg * 8;
    const int r0v = rg * 8;

    float acc[8][8];
    #pragma unroll
    for (int r = 0; r < 8; ++r)
        #pragma unroll
        for (int c = 0; c < 8; ++c) acc[r][c] = 0.f;

    for (int kc = 0; kc < D; kc += KC) {
        __syncthreads();   // previous W chunk fully consumed (and covers A/B staging)
        const float4* w1g = (const float4*)(W1 + (size_t)kc * D);
        const float4* w2g = (const float4*)(W2 + (size_t)kc * D);
        #pragma unroll
        for (int t = tid; t < KC * D / 4; t += 256) {
            ((float4*)W1c)[t] = __ldg(w1g + t);
            ((float4*)W2c)[t] = __ldg(w2g + t);
        }
        __syncthreads();

        #pragma unroll 2
        for (int kk = 0; kk < KC; ++kk) {
            const float* Ak  = At  + (kc + kk) * 128 + r0v;
            const float* Bk  = Bt  + (kc + kk) * 128 + r0v;
            const float* w1k = W1c + kk * 128 + c0;
            const float* w2k = W2c + kk * 128 + c0;
            float4 a0  = *(const float4*)Ak;        float4 a1  = *(const float4*)(Ak + 4);
            float4 e0  = *(const float4*)Bk;        float4 e1  = *(const float4*)(Bk + 4);
            float4 x0  = *(const float4*)w1k;       float4 x1  = *(const float4*)(w1k + 4);
            float4 y0  = *(const float4*)w2k;       float4 y1  = *(const float4*)(w2k + 4);
            float ar[8]  = {a0.x, a0.y, a0.z, a0.w, a1.x, a1.y, a1.z, a1.w};
            float br[8]  = {e0.x, e0.y, e0.z, e0.w, e1.x, e1.y, e1.z, e1.w};
            float w1v[8] = {x0.x, x0.y, x0.z, x0.w, x1.x, x1.y, x1.z, x1.w};
            float w2v[8] = {y0.x, y0.y, y0.z, y0.w, y1.x, y1.y, y1.z, y1.w};
            #pragma unroll
            for (int r = 0; r < 8; ++r)
                #pragma unroll
                for (int c = 0; c < 8; ++c)
                    acc[r][c] += ar[r] * w1v[c] + br[r] * w2v[c];
        }
    }

    // ---- epilogue: bias, LeakyReLU(0.2), row L2 normalize, store ----
    float4 b1a = __ldg((const float4*)(b1 + c0));
    float4 b1b = __ldg((const float4*)(b1 + c0 + 4));
    float4 b2a = __ldg((const float4*)(b2 + c0));
    float4 b2b = __ldg((const float4*)(b2 + c0 + 4));
    float bs1[8] = {b1a.x, b1a.y, b1a.z, b1a.w, b1b.x, b1b.y, b1b.z, b1b.w};
    float bs2[8] = {b2a.x, b2a.y, b2a.z, b2a.w, b2b.x, b2b.y, b2b.z, b2b.w};

    float ss[8];
    #pragma unroll
    for (int r = 0; r < 8; ++r) {
        int grow = row0 + r0v + r;
        float dg = (grow < Nrows) ? __ldg(deg + grow) : 0.f;
        float s = 0.f;
        #pragma unroll
        for (int c = 0; c < 8; ++c) {
            float h = acc[r][c] + (1.f + dg) * bs1[c] + dg * bs2[c];
            h = (h > 0.f) ? h : 0.2f * h;
            acc[r][c] = h;
            s += h * h;
        }
        ss[r] = s;
    }
    // Threads sharing a row group are 16 consecutive lanes; xor offsets <16 stay inside.
    #pragma unroll
    for (int off = 8; off >= 1; off >>= 1)
        #pragma unroll
        for (int r = 0; r < 8; ++r)
            ss[r] += __shfl_xor_sync(0xffffffffu, ss[r], off);

    #pragma unroll
    for (int r = 0; r < 8; ++r) {
        int grow = row0 + r0v + r;
        if (grow < Nrows) {
            float inv = 1.f / fmaxf(sqrtf(ss[r]), 1e-12f);
            float4 o0 = make_float4(acc[r][0] * inv, acc[r][1] * inv,
                                    acc[r][2] * inv, acc[r][3] * inv);
            float4 o1 = make_float4(acc[r][4] * inv, acc[r][5] * inv,
                                    acc[r][6] * inv, acc[r][7] * inv);
            float4* op = (float4*)(out + (size_t)grow * D + c0);
            op[0] = o0;
            op[1] = o1;
        }
    }
}

// ---------------- launch ----------------
extern "C" void kernel_launch(void* const* d_in, const int* in_sizes, int n_in,
                              void* d_out, int out_size) {
    const float* feat_user = (const float*)d_in[0];
    const float* feat_item = (const float*)d_in[1];
    const float* W1        = (const float*)d_in[2];
    const float* b1        = (const float*)d_in[3];
    const float* W2        = (const float*)d_in[4];
    const float* b2        = (const float*)d_in[5];
    const float* norm_u2i  = (const float*)d_in[6];
    const float* norm_i2u  = (const float*)d_in[7];
    const int*   e_ui_src  = (const int*)d_in[8];
    const int*   e_ui_dst  = (const int*)d_in[9];
    const int*   e_iu_src  = (const int*)d_in[10];
    const int*   e_iu_dst  = (const int*)d_in[11];
    float* out = (float*)d_out;

    const int NU = in_sizes[0] / D;
    const int NI = in_sizes[1] / D;
    const int E  = in_sizes[8];

    const int smem_bytes = (128 * 128 * 2 + KC * 128 * 2) * (int)sizeof(float);  // 192 KB
    cudaFuncSetAttribute((const void*)gemm_finish_kernel<1>,
                         cudaFuncAttributeMaxDynamicSharedMemorySize, smem_bytes);
    cudaFuncSetAttribute((const void*)gemm_finish_kernel<0>,
                         cudaFuncAttributeMaxDynamicSharedMemorySize, smem_bytes);

    zero_all_kernel<<<2048, 256>>>();

    int swarps_per_block = 256 / 32;
    int sblocks = (E + swarps_per_block - 1) / swarps_per_block;
    scatter_kernel<1><<<sblocks, 256>>>(feat_user, e_ui_src, e_ui_dst, norm_u2i, E);  // -> items
    scatter_kernel<0><<<sblocks, 256>>>(feat_item, e_iu_src, e_iu_dst, norm_i2u, E);  // -> users

    gemm_finish_kernel<1><<<(NU + 127) / 128, 256, smem_bytes>>>(
        feat_user, W1, b1, W2, b2, out, NU);
    gemm_finish_kernel<0><<<(NI + 127) / 128, 256, smem_bytes>>>(
        feat_item, W1, b1, W2, b2, out + (size_t)NU * D, NI);
}

// round 9
// speedup vs baseline: 1.7551x; 1.7551x over previous
#include <cuda_runtime.h>
#include <cuda_bf16.h>
#include <cstdint>
#include <math.h>

#define D 128
#define NU_MAX 100000
#define NI_MAX 50000

// ---------------- scratch (device globals; no allocation allowed) ----------------
__device__ float4 g_agg_user4[(size_t)NU_MAX * D / 4];
__device__ float4 g_agg_item4[(size_t)NI_MAX * D / 4];
__device__ float  g_deg_user[NU_MAX];
__device__ float  g_deg_item[NI_MAX];
// pre-split, pre-swizzled bf16 weights: tiles m = {W1hi, W1lo, W2hi, W2lo},
// each [128 n-rows][128 k] bf16, row = 256B, chunk (16B) swizzled by (n&7). 32KB/tile.
__device__ unsigned char g_wt[4 * 32768];

// ---------------- helpers ----------------
__device__ __forceinline__ uint32_t smem_u32(const void* p) {
    uint32_t a;
    asm("{ .reg .u64 t; cvta.to.shared.u64 t, %1; cvt.u32.u64 %0, t; }" : "=r"(a) : "l"(p));
    return a;
}
__device__ __forceinline__ void ldmx4(uint32_t* r, uint32_t addr) {
    asm volatile("ldmatrix.sync.aligned.m8n8.x4.shared.b16 {%0,%1,%2,%3}, [%4];"
                 : "=r"(r[0]), "=r"(r[1]), "=r"(r[2]), "=r"(r[3]) : "r"(addr));
}
__device__ __forceinline__ void mma16816(float* c, const uint32_t* a, uint32_t b0, uint32_t b1) {
    asm volatile("mma.sync.aligned.m16n8k16.row.col.f32.bf16.bf16.f32 "
                 "{%0,%1,%2,%3}, {%4,%5,%6,%7}, {%8,%9}, {%0,%1,%2,%3};"
                 : "+f"(c[0]), "+f"(c[1]), "+f"(c[2]), "+f"(c[3])
                 : "r"(a[0]), "r"(a[1]), "r"(a[2]), "r"(a[3]), "r"(b0), "r"(b1));
}
// split 8 f32 -> bf16 hi (uint4) + bf16 lo (uint4)
__device__ __forceinline__ void pack_hl(const float* v, uint4* hi, uint4* lo) {
    uint32_t h[4], l[4];
    #pragma unroll
    for (int i = 0; i < 4; ++i) {
        float2 p = make_float2(v[2 * i], v[2 * i + 1]);
        __nv_bfloat162 hb = __float22bfloat162_rn(p);
        float2 r = make_float2(p.x - __bfloat162float(hb.x),
                               p.y - __bfloat162float(hb.y));
        __nv_bfloat162 lb = __float22bfloat162_rn(r);
        h[i] = *(uint32_t*)&hb;
        l[i] = *(uint32_t*)&lb;
    }
    *hi = make_uint4(h[0], h[1], h[2], h[3]);
    *lo = make_uint4(l[0], l[1], l[2], l[3]);
}

// ---------------- zero scratch ----------------
__global__ void zero_all_kernel() {
    size_t i = (size_t)blockIdx.x * blockDim.x + threadIdx.x;
    size_t stride = (size_t)gridDim.x * blockDim.x;
    const float4 z = make_float4(0.f, 0.f, 0.f, 0.f);
    const size_t nu4 = (size_t)NU_MAX * D / 4;
    const size_t ni4 = (size_t)NI_MAX * D / 4;
    for (size_t j = i; j < nu4; j += stride) g_agg_user4[j] = z;
    for (size_t j = i; j < ni4; j += stride) g_agg_item4[j] = z;
    for (size_t j = i; j < NU_MAX; j += stride) g_deg_user[j] = 0.f;
    for (size_t j = i; j < NI_MAX; j += stride) g_deg_item[j] = 0.f;
}

// ---------------- weight prep: bf16 hi/lo split, swizzled n-major tiles ----------------
__global__ void wprep_kernel(const float* __restrict__ W1, const float* __restrict__ W2) {
    int idx = blockIdx.x * blockDim.x + threadIdx.x;   // 2*128*128
    if (idx >= 2 * D * D) return;
    int w = idx >> 14;           // 0 = W1, 1 = W2
    int k = (idx >> 7) & 127;
    int n = idx & 127;
    float v = __ldg((w ? W2 : W1) + k * D + n);
    __nv_bfloat16 hb = __float2bfloat16(v);
    __nv_bfloat16 lb = __float2bfloat16(v - __bfloat162float(hb));
    uint32_t off = (uint32_t)(n * 256 + (((k >> 3) ^ (n & 7)) * 16) + (k & 7) * 2);
    *(__nv_bfloat16*)(g_wt + (2 * w + 0) * 32768 + off) = hb;
    *(__nv_bfloat16*)(g_wt + (2 * w + 1) * 32768 + off) = lb;
}

// ---------------- per-edge scatter: agg[dst] += norm * feat_src[src] ----------------
template <int TO_ITEM>
__global__ void scatter_kernel(const float* __restrict__ feat_src,
                               const int* __restrict__ src,
                               const int* __restrict__ dst,
                               const float* __restrict__ norm,
                               int E) {
    int warp = (blockIdx.x * blockDim.x + threadIdx.x) >> 5;
    int lane = threadIdx.x & 31;
    if (warp >= E) return;
    int s = __ldg(src + warp);
    int d = __ldg(dst + warp);
    float w = __ldg(norm + warp);
    float4 f = __ldg(((const float4*)(feat_src + (size_t)s * D)) + lane);
    float* agg = TO_ITEM ? (float*)g_agg_item4 : (float*)g_agg_user4;
    float* deg = TO_ITEM ? g_deg_item : g_deg_user;
    float* addr = agg + (size_t)d * D + lane * 4;
    asm volatile("red.global.add.v4.f32 [%0], {%1, %2, %3, %4};"
                 :: "l"(addr), "f"(w * f.x), "f"(w * f.y), "f"(w * f.z), "f"(w * f.w)
                 : "memory");
    if (lane == 0) atomicAdd(deg + d, w);
}

// ---------------- mma.sync fused dual-GEMM + bias + LeakyReLU + row L2-normalize ----------------
// smem: 4 A-operand tiles (Ahi, Alo, Bhi, Blo) [128 rows][256B] swizzled = 128KB,
//       then 4 W tiles (current 64-col half) 16KB each = 64KB.  Total 192KB.
#define SM_W_OFF 131072
#define SM_TOTAL (131072 + 65536)

__global__ __launch_bounds__(256, 1)
void gemm_mma_kernel(const float* __restrict__ feat_user,
                     const float* __restrict__ feat_item,
                     const float* __restrict__ b1v,
                     const float* __restrict__ b2v,
                     float* __restrict__ out,
                     int NU, int NI, int ublocks) {
    extern __shared__ char smem[];
    const uint32_t sbase = smem_u32(smem);
    const int tid = threadIdx.x;
    const int wid = tid >> 5;
    const int lane = tid & 31;

    const bool is_user = (int)blockIdx.x < ublocks;
    const int bx = is_user ? blockIdx.x : blockIdx.x - ublocks;
    const int Nrows = is_user ? NU : NI;
    const int row0 = bx * 128;
    const float* feat = is_user ? feat_user : feat_item;
    const float* agg  = is_user ? (const float*)g_agg_user4 : (const float*)g_agg_item4;
    const float* deg  = is_user ? g_deg_user : g_deg_item;
    float* outp = is_user ? out : out + (size_t)NU * D;

    // ---- stage A-operand tiles: thread t -> row t>>1, k-half t&1 (8 chunks of 8 k) ----
    {
        int r = tid >> 1, khalf = tid & 1;
        int grow = row0 + r;
        bool valid = grow < Nrows;
        const float4* fp = (const float4*)(feat + (size_t)grow * D) + khalf * 16;
        const float4* ap = (const float4*)(agg  + (size_t)grow * D) + khalf * 16;
        const float4 z = make_float4(0.f, 0.f, 0.f, 0.f);
        uint32_t rbase = (uint32_t)(r * 256);
        int rs = r & 7;
        #pragma unroll
        for (int j = 0; j < 8; ++j) {
            float4 f0 = valid ? __ldg(fp + 2 * j)     : z;
            float4 f1 = valid ? __ldg(fp + 2 * j + 1) : z;
            float4 a0 = valid ? __ldg(ap + 2 * j)     : z;
            float4 a1 = valid ? __ldg(ap + 2 * j + 1) : z;
            float Av[8] = {f0.x + a0.x, f0.y + a0.y, f0.z + a0.z, f0.w + a0.w,
                           f1.x + a1.x, f1.y + a1.y, f1.z + a1.z, f1.w + a1.w};
            float Bv[8] = {f0.x * a0.x, f0.y * a0.y, f0.z * a0.z, f0.w * a0.w,
                           f1.x * a1.x, f1.y * a1.y, f1.z * a1.z, f1.w * a1.w};
            uint32_t off = rbase + (uint32_t)((((khalf * 8 + j) ^ rs)) * 16);
            uint4 hi, lo;
            pack_hl(Av, &hi, &lo);
            *(uint4*)(smem + 0 * 32768 + off) = hi;
            *(uint4*)(smem + 1 * 32768 + off) = lo;
            pack_hl(Bv, &hi, &lo);
            *(uint4*)(smem + 2 * 32768 + off) = hi;
            *(uint4*)(smem + 3 * 32768 + off) = lo;
        }
    }

    const int rg = wid & 3;      // rows rg*32 .. +32
    const int cg = wid >> 2;     // col group: cols h*64 + cg*32 .. +32
    const int lrow = lane & 15;  // ldmatrix row within 16-block
    const int lkh = lane >> 4;   // ldmatrix k-chunk half
    const int lswz = lrow & 7;

    float acc[2][2][4][4];       // [h][mb][nb][c0..c3]
    #pragma unroll
    for (int h = 0; h < 2; ++h)
        #pragma unroll
        for (int mb = 0; mb < 2; ++mb)
            #pragma unroll
            for (int nb = 0; nb < 4; ++nb)
                #pragma unroll
                for (int e = 0; e < 4; ++e) acc[h][mb][nb][e] = 0.f;

    const int aidx[6] = {0, 0, 1, 2, 2, 3};   // Ahi Ahi Alo Bhi Bhi Blo
    const int widx[6] = {0, 1, 0, 2, 3, 2};   // W1hi W1lo W1hi W2hi W2lo W2hi

    const uint32_t rowA0 = (uint32_t)((rg * 32 + lrow) * 256);
    const uint32_t rowA1 = rowA0 + 16 * 256;
    const uint32_t rowB0 = (uint32_t)((cg * 32 + lrow) * 256);
    const uint32_t rowB1 = rowB0 + 16 * 256;

    for (int h = 0; h < 2; ++h) {
        __syncthreads();   // first iter: A staging done; second: half-0 compute done
        // copy pre-swizzled W half (4 tiles x 16KB, contiguous n-rows slab)
        #pragma unroll
        for (int m = 0; m < 4; ++m) {
            const uint4* src = (const uint4*)(g_wt + m * 32768 + h * 16384);
            uint4* dst = (uint4*)(smem + SM_W_OFF + m * 16384);
            #pragma unroll
            for (int t = tid; t < 1024; t += 256) dst[t] = __ldg(src + t);
        }
        __syncthreads();

        #pragma unroll
        for (int p = 0; p < 6; ++p) {
            const uint32_t abase = sbase + (uint32_t)(aidx[p] * 32768);
            const uint32_t wbase = sbase + SM_W_OFF + (uint32_t)(widx[p] * 16384);
            #pragma unroll
            for (int ks = 0; ks < 8; ++ks) {
                uint32_t coff = (uint32_t)(((ks * 2 + lkh) ^ lswz) * 16);
                uint32_t a0r[4], a1r[4], b0r[4], b1r[4];
                ldmx4(a0r, abase + rowA0 + coff);
                ldmx4(a1r, abase + rowA1 + coff);
                ldmx4(b0r, wbase + rowB0 + coff);
                ldmx4(b1r, wbase + rowB1 + coff);
                #pragma unroll
                for (int mb = 0; mb < 2; ++mb) {
                    const uint32_t* a = mb ? a1r : a0r;
                    mma16816(acc[h][mb][0], a, b0r[0], b0r[2]);
                    mma16816(acc[h][mb][1], a, b0r[1], b0r[3]);
                    mma16816(acc[h][mb][2], a, b1r[0], b1r[2]);
                    mma16816(acc[h][mb][3], a, b1r[1], b1r[3]);
                }
            }
        }
    }
    __syncthreads();   // compute fully done before smem reuse

    // ---- epilogue: bias, LeakyReLU(0.2), row L2 normalize, store ----
    // C frag: c0,c1 -> row lane>>2, cols (lane&3)*2 +{0,1}; c2,c3 -> row+8.
    const int rl = lane >> 2;
    float dg[2][2], ss[2][2];
    #pragma unroll
    for (int mb = 0; mb < 2; ++mb)
        #pragma unroll
        for (int rh = 0; rh < 2; ++rh) {
            int grow = row0 + rg * 32 + mb * 16 + rh * 8 + rl;
            dg[mb][rh] = (grow < Nrows) ? __ldg(deg + grow) : 0.f;
            ss[mb][rh] = 0.f;
        }

    #pragma unroll
    for (int h = 0; h < 2; ++h)
        #pragma unroll
        for (int nb = 0; nb < 4; ++nb) {
            int col = h * 64 + cg * 32 + nb * 8 + (lane & 3) * 2;
            float2 bb1 = __ldg((const float2*)(b1v + col));
            float2 bb2 = __ldg((const float2*)(b2v + col));
            #pragma unroll
            for (int mb = 0; mb < 2; ++mb)
                #pragma unroll
                for (int rh = 0; rh < 2; ++rh) {
                    float d = dg[mb][rh];
                    float* c = acc[h][mb][nb] + rh * 2;
                    float h0 = c[0] + (1.f + d) * bb1.x + d * bb2.x;
                    float h1 = c[1] + (1.f + d) * bb1.y + d * bb2.y;
                    h0 = (h0 > 0.f) ? h0 : 0.2f * h0;
                    h1 = (h1 > 0.f) ? h1 : 0.2f * h1;
                    c[0] = h0; c[1] = h1;
                    ss[mb][rh] += h0 * h0 + h1 * h1;
                }
        }
    // reduce over the 4 lanes of each row quad
    #pragma unroll
    for (int off = 1; off <= 2; off <<= 1)
        #pragma unroll
        for (int mb = 0; mb < 2; ++mb)
            #pragma unroll
            for (int rh = 0; rh < 2; ++rh)
                ss[mb][rh] += __shfl_xor_sync(0xffffffffu, ss[mb][rh], off);

    // exchange partial sumsq between the two col-group warp sets
    float* part = (float*)smem;    // [2 cg][128 rows]
    if ((lane & 3) == 0) {
        #pragma unroll
        for (int mb = 0; mb < 2; ++mb)
            #pragma unroll
            for (int rh = 0; rh < 2; ++rh)
                part[cg * 128 + rg * 32 + mb * 16 + rh * 8 + rl] = ss[mb][rh];
    }
    __syncthreads();

    #pragma unroll
    for (int mb = 0; mb < 2; ++mb)
        #pragma unroll
        for (int rh = 0; rh < 2; ++rh) {
            int lrow128 = rg * 32 + mb * 16 + rh * 8 + rl;
            int grow = row0 + lrow128;
            float tot = ss[mb][rh] + part[(1 ^ cg) * 128 + lrow128];
            float inv = 1.f / fmaxf(sqrtf(tot), 1e-12f);
            if (grow < Nrows) {
                #pragma unroll
                for (int h = 0; h < 2; ++h)
                    #pragma unroll
                    for (int nb = 0; nb < 4; ++nb) {
                        int col = h * 64 + cg * 32 + nb * 8 + (lane & 3) * 2;
                        float* c = acc[h][mb][nb] + rh * 2;
                        *(float2*)(outp + (size_t)grow * D + col) =
                            make_float2(c[0] * inv, c[1] * inv);
                    }
            }
        }
}

// ---------------- launch ----------------
extern "C" void kernel_launch(void* const* d_in, const int* in_sizes, int n_in,
                              void* d_out, int out_size) {
    const float* feat_user = (const float*)d_in[0];
    const float* feat_item = (const float*)d_in[1];
    const float* W1        = (const float*)d_in[2];
    const float* b1        = (const float*)d_in[3];
    const float* W2        = (const float*)d_in[4];
    const float* b2        = (const float*)d_in[5];
    const float* norm_u2i  = (const float*)d_in[6];
    const float* norm_i2u  = (const float*)d_in[7];
    const int*   e_ui_src  = (const int*)d_in[8];
    const int*   e_ui_dst  = (const int*)d_in[9];
    const int*   e_iu_src  = (const int*)d_in[10];
    const int*   e_iu_dst  = (const int*)d_in[11];
    float* out = (float*)d_out;

    const int NU = in_sizes[0] / D;
    const int NI = in_sizes[1] / D;
    const int E  = in_sizes[8];

    cudaFuncSetAttribute((const void*)gemm_mma_kernel,
                         cudaFuncAttributeMaxDynamicSharedMemorySize, SM_TOTAL);

    zero_all_kernel<<<2048, 256>>>();
    wprep_kernel<<<(2 * D * D + 255) / 256, 256>>>(W1, W2);

    int sblocks = (E + 7) / 8;
    scatter_kernel<1><<<sblocks, 256>>>(feat_user, e_ui_src, e_ui_dst, norm_u2i, E);
    scatter_kernel<0><<<sblocks, 256>>>(feat_item, e_iu_src, e_iu_dst, norm_i2u, E);

    const int ublocks = (NU + 127) / 128;
    const int iblocks = (NI + 127) / 128;
    gemm_mma_kernel<<<ublocks + iblocks, 256, SM_TOTAL>>>(
        feat_user, feat_item, b1, b2, out, NU, NI, ublocks);
}